// round 15
// baseline (speedup 1.0000x reference)
#include <cuda_runtime.h>
#include <cuda_fp16.h>
#include <math.h>
#include <stdint.h>

// Problem constants
#define BATCH 4
#define SEQ   2048
#define DIM   768
#define NQKV  (3 * DIM)        // 2304

// Scratch (allocation-free: __device__ globals)
__device__ __half g_xh  [(size_t)BATCH * SEQ * DIM];
__device__ __half g_qkv [(size_t)BATCH * SEQ * NQKV];
__device__ __half g_vt  [(size_t)BATCH * SEQ * DIM];
__device__ __half g_s   [(size_t)BATCH * SEQ * SEQ];   // fp16 scores -> probs (in place)
__device__ __half g_wt  [(size_t)NQKV * DIM];
__device__ float  g_bc  [NQKV];

// ----------------------------------------------------------------------------
// helpers
// ----------------------------------------------------------------------------
__device__ __forceinline__ uint32_t smem_u32(const void* p) {
    uint32_t a;
    asm("{ .reg .u64 t; cvta.to.shared.u64 t, %1; cvt.u32.u64 %0, t; }"
        : "=r"(a) : "l"(p));
    return a;
}
__device__ __forceinline__ void cp_async16(uint32_t dst, const void* src) {
    asm volatile("cp.async.cg.shared.global [%0], [%1], 16;"
                 :: "r"(dst), "l"(src));
}
__device__ __forceinline__ void cp_commit() {
    asm volatile("cp.async.commit_group;" ::: "memory");
}
template <int N>
__device__ __forceinline__ void cp_wait() {
    asm volatile("cp.async.wait_group %0;" :: "n"(N) : "memory");
}
__device__ __forceinline__ void ldsm_x4(uint32_t* r, uint32_t addr) {
    asm volatile("ldmatrix.sync.aligned.m8n8.x4.shared.b16 {%0,%1,%2,%3}, [%4];"
                 : "=r"(r[0]), "=r"(r[1]), "=r"(r[2]), "=r"(r[3])
                 : "r"(addr));
}
__device__ __forceinline__ void mma_f16(float* c, const uint32_t* a,
                                        uint32_t b0, uint32_t b1) {
    asm volatile(
        "mma.sync.aligned.m16n8k16.row.col.f32.f16.f16.f32 "
        "{%0,%1,%2,%3}, {%4,%5,%6,%7}, {%8,%9}, {%0,%1,%2,%3};"
        : "+f"(c[0]), "+f"(c[1]), "+f"(c[2]), "+f"(c[3])
        : "r"(a[0]), "r"(a[1]), "r"(a[2]), "r"(a[3]),
          "r"(b0), "r"(b1));
}

// ----------------------------------------------------------------------------
// fp16 tensor-core GEMM (NT): C = scale * (A @ B^T + bias)
//   A: [M,K] half row-major (lda), B: [N,K] half row-major (ldb)
//   C: [M,N] float or half (ldc). fp32 accumulate.
//   CTA tile 128x128, 4 warps, warp tile 64x64 (4x8 m16n8k16 atoms).
//   BK=64, 3-stage cp.async pipeline. SMEM row stride 72 halfs (144B).
//   QKVF: per-column scale — cols < DIM get alpha (Q pre-scale), else 1.
// ----------------------------------------------------------------------------
#define SH        72
#define MAT_H     (128 * SH)
#define STAGE_H   (2 * MAT_H)            // A tile + B tile (halfs)
#define NSTAGE    3

template <typename CT, bool BIAS, bool QKVF>
__global__ __launch_bounds__(128)
void gemm_h(const __half* __restrict__ A, const __half* __restrict__ B,
            const float* __restrict__ bias, CT* __restrict__ C,
            int K, int lda, int ldb, int ldc, float alpha,
            size_t sA, size_t sB, size_t sC)
{
    extern __shared__ __half smh[];

    const int tid  = threadIdx.x;
    const int wid  = tid >> 5;
    const int lane = tid & 31;
    const int grp  = lane >> 2;
    const int tg   = lane & 3;
    const int wm0  = (wid & 1) * 64;
    const int wn0  = (wid >> 1) * 64;
    const int lg   = lane >> 3;
    const int lrow = lane & 7;

    A += (size_t)blockIdx.z * sA;
    B += (size_t)blockIdx.z * sB;
    C += (size_t)blockIdx.z * sC;
    const int m0 = blockIdx.y * 128;
    const int n0 = blockIdx.x * 128;

    // gmem->smem: 16B granules; 8 segs per 64-half row; 128 threads
    const int ld_row = tid >> 3;        // 0..15 (+16 per pass, 8 passes)
    const int ld_seg = tid & 7;

    float acc[4][8][4];
#pragma unroll
    for (int im = 0; im < 4; im++)
#pragma unroll
        for (int in = 0; in < 8; in++)
#pragma unroll
            for (int r = 0; r < 4; r++) acc[im][in][r] = 0.0f;

    const int nch = K >> 6;

    auto load_tile = [&](int c) {
        const int kt = c << 6;
        __half* as = smh + (c % NSTAGE) * STAGE_H;
        __half* bs = as + MAT_H;
        const uint32_t as_u = smem_u32(as);
        const uint32_t bs_u = smem_u32(bs);
#pragma unroll
        for (int r = 0; r < 8; r++) {
            const int row = ld_row + r * 16;
            cp_async16(as_u + (uint32_t)(row * SH + ld_seg * 8) * 2,
                       A + (size_t)(m0 + row) * lda + kt + ld_seg * 8);
        }
#pragma unroll
        for (int r = 0; r < 8; r++) {
            const int row = ld_row + r * 16;
            cp_async16(bs_u + (uint32_t)(row * SH + ld_seg * 8) * 2,
                       B + (size_t)(n0 + row) * ldb + kt + ld_seg * 8);
        }
    };

    load_tile(0);
    cp_commit();
    load_tile(1);
    cp_commit();

    for (int c = 0; c < nch; c++) {
        cp_wait<1>();          // stage c resident (c+1 may be in flight)
        __syncthreads();       // visibility + all warps done with stage c-1

        if (c + 2 < nch) {     // prefetch into buffer (c+2)%3 == (c-1)%3 (free)
            load_tile(c + 2);
            cp_commit();
        }

        const __half* as = smh + (c % NSTAGE) * STAGE_H;
        const __half* bs = as + MAT_H;

        const uint32_t a_base = smem_u32(as) +
            (uint32_t)(((wm0 + (lg & 1) * 8 + lrow) * SH + (lg >> 1) * 8) * 2);
        const uint32_t b_base = smem_u32(bs) +
            (uint32_t)(((wn0 + (lg & 1) * 8 + lrow) * SH + (lg >> 1) * 8) * 2);

#pragma unroll
        for (int ks = 0; ks < 4; ks++) {
            uint32_t af[4][4];
#pragma unroll
            for (int im = 0; im < 4; im++)
                ldsm_x4(af[im], a_base + im * (16 * SH * 2) + ks * 32);
            uint32_t bf[4][4];   // bf[p]: n-tiles 2p,2p+1 (k0-7 then k8-15)
#pragma unroll
            for (int p = 0; p < 4; p++)
                ldsm_x4(bf[p], b_base + p * (16 * SH * 2) + ks * 32);
#pragma unroll
            for (int im = 0; im < 4; im++)
#pragma unroll
                for (int in = 0; in < 8; in++)
                    mma_f16(acc[im][in], af[im],
                            bf[in >> 1][in & 1], bf[in >> 1][(in & 1) + 2]);
        }
    }
    cp_wait<0>();

    // ---- epilogue ----
#pragma unroll
    for (int im = 0; im < 4; im++) {
        const int row = m0 + wm0 + im * 16 + grp;
#pragma unroll
        for (int in = 0; in < 8; in++) {
            const int col = n0 + wn0 + in * 8 + tg * 2;
            const float sc = (!QKVF || col < DIM) ? alpha : 1.0f;
            float2 v01, v23;
            v01.x = acc[im][in][0];
            v01.y = acc[im][in][1];
            v23.x = acc[im][in][2];
            v23.y = acc[im][in][3];
            if (BIAS) {
                const float2 bv = *reinterpret_cast<const float2*>(bias + col);
                v01.x += bv.x; v01.y += bv.y;
                v23.x += bv.x; v23.y += bv.y;
            }
            v01.x *= sc; v01.y *= sc; v23.x *= sc; v23.y *= sc;
            if (sizeof(CT) == 2) {
                *reinterpret_cast<__half2*>((__half*)C + (size_t)row * ldc + col)
                    = __floats2half2_rn(v01.x, v01.y);
                *reinterpret_cast<__half2*>((__half*)C + (size_t)(row + 8) * ldc + col)
                    = __floats2half2_rn(v23.x, v23.y);
            } else {
                *reinterpret_cast<float2*>((float*)C + (size_t)row * ldc + col) = v01;
                *reinterpret_cast<float2*>((float*)C + (size_t)(row + 8) * ldc + col) = v23;
            }
        }
    }
}

// ----------------------------------------------------------------------------
// fp32 -> fp16 elementwise copy
// ----------------------------------------------------------------------------
__global__ __launch_bounds__(256)
void f32_to_f16(const float* __restrict__ src, __half* __restrict__ dst)
{
    const int i = blockIdx.x * blockDim.x + threadIdx.x;
    const float4 v = reinterpret_cast<const float4*>(src)[i];
    __half2* d = reinterpret_cast<__half2*>(dst) + i * 2;
    d[0] = __floats2half2_rn(v.x, v.y);
    d[1] = __floats2half2_rn(v.z, v.w);
}

// ----------------------------------------------------------------------------
// batched 32x32 transpose of the three DIM x DIM weights, fp32 -> fp16:
//   dst[z][c*DIM + r] = (half)Wz[r*DIM + c]
// ----------------------------------------------------------------------------
__global__ __launch_bounds__(256)
void trans_w3(const float* __restrict__ w0, const float* __restrict__ w1,
              const float* __restrict__ w2, __half* __restrict__ dst)
{
    __shared__ float t[32][33];
    const float* src = (blockIdx.z == 0) ? w0 : (blockIdx.z == 1) ? w1 : w2;
    __half* d = dst + (size_t)blockIdx.z * DIM * DIM;
    const int r0 = blockIdx.y * 32, c0 = blockIdx.x * 32;
    const int tx = threadIdx.x & 31, ty = threadIdx.x >> 5;
#pragma unroll
    for (int i = 0; i < 4; i++)
        t[ty + 8 * i][tx] = src[(size_t)(r0 + ty + 8 * i) * DIM + c0 + tx];
    __syncthreads();
#pragma unroll
    for (int i = 0; i < 4; i++)
        d[(size_t)(c0 + ty + 8 * i) * DIM + r0 + tx] =
            __float2half_rn(t[tx][ty + 8 * i]);
}

// ----------------------------------------------------------------------------
// 32x32 tiled transpose fp16->fp16 with src leading dim (batched via z)
//   dst[c*Rd + r] = src[r*ldS + c]
// ----------------------------------------------------------------------------
__global__ __launch_bounds__(256)
void trans_h2h(const __half* __restrict__ src, __half* __restrict__ dst,
               int Rd, int ldS, size_t sS, size_t sD)
{
    __shared__ __half t[32][34];
    src += (size_t)blockIdx.z * sS;
    dst += (size_t)blockIdx.z * sD;
    const int r0 = blockIdx.y * 32, c0 = blockIdx.x * 32;
    const int tx = threadIdx.x & 31, ty = threadIdx.x >> 5;
#pragma unroll
    for (int i = 0; i < 4; i++)
        t[ty + 8 * i][tx] = src[(size_t)(r0 + ty + 8 * i) * ldS + c0 + tx];
    __syncthreads();
#pragma unroll
    for (int i = 0; i < 4; i++)
        dst[(size_t)(c0 + ty + 8 * i) * Rd + r0 + tx] = t[tx][ty + 8 * i];
}

// ----------------------------------------------------------------------------
// bias concat: bc[0:768)=bq, [768:1536)=bk, [1536:2304)=bv
// ----------------------------------------------------------------------------
__global__ void concat_bias(const float* __restrict__ bq,
                            const float* __restrict__ bk,
                            const float* __restrict__ bv,
                            float* __restrict__ bc)
{
    const int i = blockIdx.x * blockDim.x + threadIdx.x;
    if (i < DIM)            bc[i] = bq[i];
    else if (i < 2 * DIM)   bc[i] = bk[i - DIM];
    else if (i < 3 * DIM)   bc[i] = bv[i - 2 * DIM];
}

// ----------------------------------------------------------------------------
// In-place row softmax over SEQ=2048 fp16 values. One block (256 thr) per row.
// Each thread owns one uint4 = 8 halfs.
// ----------------------------------------------------------------------------
__global__ __launch_bounds__(256)
void softmax2048_h(__half* __restrict__ S)
{
    uint4* row = reinterpret_cast<uint4*>(S + (size_t)blockIdx.x * SEQ);
    const int tid = threadIdx.x;
    __shared__ float red_max[8];
    __shared__ float red_sum[8];

    const uint4 raw = row[tid];
    const __half2* h2 = reinterpret_cast<const __half2*>(&raw);
    float v[8];
#pragma unroll
    for (int i = 0; i < 4; i++) {
        const float2 f = __half22float2(h2[i]);
        v[2 * i] = f.x;
        v[2 * i + 1] = f.y;
    }

    float m = v[0];
#pragma unroll
    for (int i = 1; i < 8; i++) m = fmaxf(m, v[i]);
#pragma unroll
    for (int o = 16; o > 0; o >>= 1)
        m = fmaxf(m, __shfl_xor_sync(0xffffffffu, m, o));
    if ((tid & 31) == 0) red_max[tid >> 5] = m;
    __syncthreads();
    float rm = red_max[0];
#pragma unroll
    for (int i = 1; i < 8; i++) rm = fmaxf(rm, red_max[i]);

    float s = 0.0f;
#pragma unroll
    for (int i = 0; i < 8; i++) {
        v[i] = __expf(v[i] - rm);
        s += v[i];
    }
#pragma unroll
    for (int o = 16; o > 0; o >>= 1)
        s += __shfl_xor_sync(0xffffffffu, s, o);
    if ((tid & 31) == 0) red_sum[tid >> 5] = s;
    __syncthreads();
    float total = 0.0f;
#pragma unroll
    for (int i = 0; i < 8; i++) total += red_sum[i];
    const float inv = 1.0f / total;

    uint4 outw;
    __half2* o2 = reinterpret_cast<__half2*>(&outw);
#pragma unroll
    for (int i = 0; i < 4; i++)
        o2[i] = __floats2half2_rn(v[2 * i] * inv, v[2 * i + 1] * inv);
    row[tid] = outw;
}

// ----------------------------------------------------------------------------
// kernel_launch
// Inputs: x[B,S,D], Wq[D,D], bq[D], Wk, bk, Wv, bv ; output [B,S,D] fp32
// ----------------------------------------------------------------------------
extern "C" void kernel_launch(void* const* d_in, const int* in_sizes, int n_in,
                              void* d_out, int out_size)
{
    const float* x  = (const float*)d_in[0];
    const float* Wq = (const float*)d_in[1];
    const float* bq = (const float*)d_in[2];
    const float* Wk = (const float*)d_in[3];
    const float* bk = (const float*)d_in[4];
    const float* Wv = (const float*)d_in[5];
    const float* bv = (const float*)d_in[6];
    float* out = (float*)d_out;

    __half *xh, *qkv, *vt, *s, *wt;
    float *bc;
    cudaGetSymbolAddress((void**)&xh,  g_xh);
    cudaGetSymbolAddress((void**)&qkv, g_qkv);
    cudaGetSymbolAddress((void**)&vt,  g_vt);
    cudaGetSymbolAddress((void**)&s,   g_s);
    cudaGetSymbolAddress((void**)&wt,  g_wt);
    cudaGetSymbolAddress((void**)&bc,  g_bc);

    const int SMEM_DYN = NSTAGE * STAGE_H * (int)sizeof(__half);   // 110592 B
    cudaFuncSetAttribute((const void*)gemm_h<__half, true, true>,
                         cudaFuncAttributeMaxDynamicSharedMemorySize, SMEM_DYN);
    cudaFuncSetAttribute((const void*)gemm_h<__half, false, false>,
                         cudaFuncAttributeMaxDynamicSharedMemorySize, SMEM_DYN);
    cudaFuncSetAttribute((const void*)gemm_h<float, false, false>,
                         cudaFuncAttributeMaxDynamicSharedMemorySize, SMEM_DYN);

    const size_t sQKV = (size_t)SEQ * NQKV;   // per-batch qkv stride
    const size_t sSD  = (size_t)SEQ * DIM;
    const size_t sSS  = (size_t)SEQ * SEQ;

    // 0) x -> fp16 ; W -> half(W^T) concatenated (one launch) ; bias concat
    f32_to_f16<<<(BATCH * SEQ * DIM / 4 + 255) / 256, 256>>>(x, xh);
    {
        const dim3 g(DIM / 32, DIM / 32, 3);
        trans_w3<<<g, 256>>>(Wq, Wk, Wv, wt);
    }
    concat_bias<<<(NQKV + 255) / 256, 256>>>(bq, bk, bv, bc);

    // 1) fused QKV: [8192,2304] = x @ Wcat^T + bcat ; Q slice pre-scaled 1/sqrt(D)
    {
        const dim3 g(NQKV / 128, (BATCH * SEQ) / 128, 1);
        gemm_h<__half, true, true><<<g, 128, SMEM_DYN>>>(
            xh, wt, bc, qkv, DIM, DIM, DIM, NQKV,
            rsqrtf((float)DIM), 0, 0, 0);
    }

    // 2) transpose V slice: [S, D] (ld=NQKV) -> vt [D, S] per batch
    {
        const dim3 g(DIM / 32, SEQ / 32, BATCH);
        trans_h2h<<<g, 256>>>(qkv + 2 * DIM, vt, SEQ, NQKV, sQKV, sSD);
    }

    // 3) scores = Qs @ K^T  (Q already scaled; NT, fp16 out)
    {
        const dim3 g(SEQ / 128, SEQ / 128, BATCH);
        gemm_h<__half, false, false><<<g, 128, SMEM_DYN>>>(
            qkv, qkv + DIM, nullptr, s, DIM, NQKV, NQKV, SEQ,
            1.0f, sQKV, sQKV, sSS);
    }

    // 4) in-place softmax rows (fp16 -> fp16 probs; matrix stays L2-resident)
    softmax2048_h<<<BATCH * SEQ, 256>>>(s);

    // 5) out = P @ V == s[S,S] @ (vt[D,S])^T  (NT, fp32 out)
    {
        const dim3 g(DIM / 128, SEQ / 128, BATCH);
        gemm_h<float, false, false><<<g, 128, SMEM_DYN>>>(
            s, vt, nullptr, out, SEQ, SEQ, SEQ, DIM,
            1.0f, sSS, sSD, sSD);
    }
}

// round 16
// speedup vs baseline: 1.0032x; 1.0032x over previous
#include <cuda_runtime.h>
#include <cuda_fp16.h>
#include <math.h>
#include <stdint.h>

// Problem constants
#define BATCH 4
#define SEQ   2048
#define DIM   768
#define NQKV  (3 * DIM)        // 2304

// Scratch (allocation-free: __device__ globals)
__device__ __half g_xh  [(size_t)BATCH * SEQ * DIM];
__device__ __half g_qkv [(size_t)BATCH * SEQ * NQKV];
__device__ __half g_vt  [(size_t)BATCH * SEQ * DIM];
__device__ __half g_s   [(size_t)BATCH * SEQ * SEQ];   // fp16 scores -> probs (in place)
__device__ __half g_wt  [(size_t)NQKV * DIM];
__device__ float  g_bc  [NQKV];

// ----------------------------------------------------------------------------
// helpers
// ----------------------------------------------------------------------------
__device__ __forceinline__ uint32_t smem_u32(const void* p) {
    uint32_t a;
    asm("{ .reg .u64 t; cvta.to.shared.u64 t, %1; cvt.u32.u64 %0, t; }"
        : "=r"(a) : "l"(p));
    return a;
}
__device__ __forceinline__ void cp_async16(uint32_t dst, const void* src) {
    asm volatile("cp.async.cg.shared.global [%0], [%1], 16;"
                 :: "r"(dst), "l"(src));
}
__device__ __forceinline__ void cp_commit() {
    asm volatile("cp.async.commit_group;" ::: "memory");
}
template <int N>
__device__ __forceinline__ void cp_wait() {
    asm volatile("cp.async.wait_group %0;" :: "n"(N) : "memory");
}
__device__ __forceinline__ void ldsm_x4(uint32_t* r, uint32_t addr) {
    asm volatile("ldmatrix.sync.aligned.m8n8.x4.shared.b16 {%0,%1,%2,%3}, [%4];"
                 : "=r"(r[0]), "=r"(r[1]), "=r"(r[2]), "=r"(r[3])
                 : "r"(addr));
}
__device__ __forceinline__ void mma_f16(float* c, const uint32_t* a,
                                        uint32_t b0, uint32_t b1) {
    asm volatile(
        "mma.sync.aligned.m16n8k16.row.col.f32.f16.f16.f32 "
        "{%0,%1,%2,%3}, {%4,%5,%6,%7}, {%8,%9}, {%0,%1,%2,%3};"
        : "+f"(c[0]), "+f"(c[1]), "+f"(c[2]), "+f"(c[3])
        : "r"(a[0]), "r"(a[1]), "r"(a[2]), "r"(a[3]),
          "r"(b0), "r"(b1));
}

// ----------------------------------------------------------------------------
// fp16 tensor-core GEMM (NT): C = scale * (A @ B^T + bias)
//   A: [M,K] half row-major (lda), B: [N,K] half row-major (ldb)
//   C: [M,N] float or half (ldc). fp32 accumulate.
//   CTA tile 128x128, 4 warps, warp tile 64x64 (4x8 m16n8k16 atoms).
//   BK=64, 3-stage cp.async pipeline. SMEM row stride 72 halfs (144B).
//   QKVF: per-column scale — cols < DIM get alpha (Q pre-scale), else 1.
// ----------------------------------------------------------------------------
#define SH        72
#define MAT_H     (128 * SH)
#define STAGE_H   (2 * MAT_H)            // A tile + B tile (halfs)
#define NSTAGE    3

template <typename CT, bool BIAS, bool QKVF>
__global__ __launch_bounds__(128)
void gemm_h(const __half* __restrict__ A, const __half* __restrict__ B,
            const float* __restrict__ bias, CT* __restrict__ C,
            int K, int lda, int ldb, int ldc, float alpha,
            size_t sA, size_t sB, size_t sC)
{
    extern __shared__ __half smh[];

    const int tid  = threadIdx.x;
    const int wid  = tid >> 5;
    const int lane = tid & 31;
    const int grp  = lane >> 2;
    const int tg   = lane & 3;
    const int wm0  = (wid & 1) * 64;
    const int wn0  = (wid >> 1) * 64;
    const int lg   = lane >> 3;
    const int lrow = lane & 7;

    A += (size_t)blockIdx.z * sA;
    B += (size_t)blockIdx.z * sB;
    C += (size_t)blockIdx.z * sC;
    const int m0 = blockIdx.y * 128;
    const int n0 = blockIdx.x * 128;

    // gmem->smem: 16B granules; 8 segs per 64-half row; 128 threads
    const int ld_row = tid >> 3;        // 0..15 (+16 per pass, 8 passes)
    const int ld_seg = tid & 7;

    float acc[4][8][4];
#pragma unroll
    for (int im = 0; im < 4; im++)
#pragma unroll
        for (int in = 0; in < 8; in++)
#pragma unroll
            for (int r = 0; r < 4; r++) acc[im][in][r] = 0.0f;

    const int nch = K >> 6;

    auto load_tile = [&](int c) {
        const int kt = c << 6;
        __half* as = smh + (c % NSTAGE) * STAGE_H;
        __half* bs = as + MAT_H;
        const uint32_t as_u = smem_u32(as);
        const uint32_t bs_u = smem_u32(bs);
#pragma unroll
        for (int r = 0; r < 8; r++) {
            const int row = ld_row + r * 16;
            cp_async16(as_u + (uint32_t)(row * SH + ld_seg * 8) * 2,
                       A + (size_t)(m0 + row) * lda + kt + ld_seg * 8);
        }
#pragma unroll
        for (int r = 0; r < 8; r++) {
            const int row = ld_row + r * 16;
            cp_async16(bs_u + (uint32_t)(row * SH + ld_seg * 8) * 2,
                       B + (size_t)(n0 + row) * ldb + kt + ld_seg * 8);
        }
    };

    load_tile(0);
    cp_commit();
    load_tile(1);
    cp_commit();

    for (int c = 0; c < nch; c++) {
        cp_wait<1>();          // stage c resident (c+1 may be in flight)
        __syncthreads();       // visibility + all warps done with stage c-1

        if (c + 2 < nch) {     // prefetch into buffer (c+2)%3 == (c-1)%3 (free)
            load_tile(c + 2);
            cp_commit();
        }

        const __half* as = smh + (c % NSTAGE) * STAGE_H;
        const __half* bs = as + MAT_H;

        const uint32_t a_base = smem_u32(as) +
            (uint32_t)(((wm0 + (lg & 1) * 8 + lrow) * SH + (lg >> 1) * 8) * 2);
        const uint32_t b_base = smem_u32(bs) +
            (uint32_t)(((wn0 + (lg & 1) * 8 + lrow) * SH + (lg >> 1) * 8) * 2);

#pragma unroll
        for (int ks = 0; ks < 4; ks++) {
            uint32_t af[4][4];
#pragma unroll
            for (int im = 0; im < 4; im++)
                ldsm_x4(af[im], a_base + im * (16 * SH * 2) + ks * 32);
            uint32_t bf[4][4];   // bf[p]: n-tiles 2p,2p+1 (k0-7 then k8-15)
#pragma unroll
            for (int p = 0; p < 4; p++)
                ldsm_x4(bf[p], b_base + p * (16 * SH * 2) + ks * 32);
#pragma unroll
            for (int im = 0; im < 4; im++)
#pragma unroll
                for (int in = 0; in < 8; in++)
                    mma_f16(acc[im][in], af[im],
                            bf[in >> 1][in & 1], bf[in >> 1][(in & 1) + 2]);
        }
    }
    cp_wait<0>();

    // ---- epilogue ----
#pragma unroll
    for (int im = 0; im < 4; im++) {
        const int row = m0 + wm0 + im * 16 + grp;
#pragma unroll
        for (int in = 0; in < 8; in++) {
            const int col = n0 + wn0 + in * 8 + tg * 2;
            const float sc = (!QKVF || col < DIM) ? alpha : 1.0f;
            float2 v01, v23;
            v01.x = acc[im][in][0];
            v01.y = acc[im][in][1];
            v23.x = acc[im][in][2];
            v23.y = acc[im][in][3];
            if (BIAS) {
                const float2 bv = *reinterpret_cast<const float2*>(bias + col);
                v01.x += bv.x; v01.y += bv.y;
                v23.x += bv.x; v23.y += bv.y;
            }
            v01.x *= sc; v01.y *= sc; v23.x *= sc; v23.y *= sc;
            if (sizeof(CT) == 2) {
                *reinterpret_cast<__half2*>((__half*)C + (size_t)row * ldc + col)
                    = __floats2half2_rn(v01.x, v01.y);
                *reinterpret_cast<__half2*>((__half*)C + (size_t)(row + 8) * ldc + col)
                    = __floats2half2_rn(v23.x, v23.y);
            } else {
                *reinterpret_cast<float2*>((float*)C + (size_t)row * ldc + col) = v01;
                *reinterpret_cast<float2*>((float*)C + (size_t)(row + 8) * ldc + col) = v23;
            }
        }
    }
}

// ----------------------------------------------------------------------------
// fp32 -> fp16 elementwise copy
// ----------------------------------------------------------------------------
__global__ __launch_bounds__(256)
void f32_to_f16(const float* __restrict__ src, __half* __restrict__ dst)
{
    const int i = blockIdx.x * blockDim.x + threadIdx.x;
    const float4 v = reinterpret_cast<const float4*>(src)[i];
    __half2* d = reinterpret_cast<__half2*>(dst) + i * 2;
    d[0] = __floats2half2_rn(v.x, v.y);
    d[1] = __floats2half2_rn(v.z, v.w);
}

// ----------------------------------------------------------------------------
// batched 32x32 transpose of the three DIM x DIM weights, fp32 -> fp16:
//   dst[z][c*DIM + r] = (half)Wz[r*DIM + c]
// ----------------------------------------------------------------------------
__global__ __launch_bounds__(256)
void trans_w3(const float* __restrict__ w0, const float* __restrict__ w1,
              const float* __restrict__ w2, __half* __restrict__ dst)
{
    __shared__ float t[32][33];
    const float* src = (blockIdx.z == 0) ? w0 : (blockIdx.z == 1) ? w1 : w2;
    __half* d = dst + (size_t)blockIdx.z * DIM * DIM;
    const int r0 = blockIdx.y * 32, c0 = blockIdx.x * 32;
    const int tx = threadIdx.x & 31, ty = threadIdx.x >> 5;
#pragma unroll
    for (int i = 0; i < 4; i++)
        t[ty + 8 * i][tx] = src[(size_t)(r0 + ty + 8 * i) * DIM + c0 + tx];
    __syncthreads();
#pragma unroll
    for (int i = 0; i < 4; i++)
        d[(size_t)(c0 + ty + 8 * i) * DIM + r0 + tx] =
            __float2half_rn(t[tx][ty + 8 * i]);
}

// ----------------------------------------------------------------------------
// 32x32 tiled transpose fp16->fp16 with src leading dim (batched via z)
//   dst[c*Rd + r] = src[r*ldS + c]
// ----------------------------------------------------------------------------
__global__ __launch_bounds__(256)
void trans_h2h(const __half* __restrict__ src, __half* __restrict__ dst,
               int Rd, int ldS, size_t sS, size_t sD)
{
    __shared__ __half t[32][34];
    src += (size_t)blockIdx.z * sS;
    dst += (size_t)blockIdx.z * sD;
    const int r0 = blockIdx.y * 32, c0 = blockIdx.x * 32;
    const int tx = threadIdx.x & 31, ty = threadIdx.x >> 5;
#pragma unroll
    for (int i = 0; i < 4; i++)
        t[ty + 8 * i][tx] = src[(size_t)(r0 + ty + 8 * i) * ldS + c0 + tx];
    __syncthreads();
#pragma unroll
    for (int i = 0; i < 4; i++)
        dst[(size_t)(c0 + ty + 8 * i) * Rd + r0 + tx] = t[tx][ty + 8 * i];
}

// ----------------------------------------------------------------------------
// bias concat: bc[0:768)=bq, [768:1536)=bk, [1536:2304)=bv
// ----------------------------------------------------------------------------
__global__ void concat_bias(const float* __restrict__ bq,
                            const float* __restrict__ bk,
                            const float* __restrict__ bv,
                            float* __restrict__ bc)
{
    const int i = blockIdx.x * blockDim.x + threadIdx.x;
    if (i < DIM)            bc[i] = bq[i];
    else if (i < 2 * DIM)   bc[i] = bk[i - DIM];
    else if (i < 3 * DIM)   bc[i] = bv[i - 2 * DIM];
}

// ----------------------------------------------------------------------------
// In-place row softmax over SEQ=2048 fp16 values. One block (256 thr) per row.
// Each thread owns one uint4 = 8 halfs.
// ----------------------------------------------------------------------------
__global__ __launch_bounds__(256)
void softmax2048_h(__half* __restrict__ S)
{
    uint4* row = reinterpret_cast<uint4*>(S + (size_t)blockIdx.x * SEQ);
    const int tid = threadIdx.x;
    __shared__ float red_max[8];
    __shared__ float red_sum[8];

    const uint4 raw = row[tid];
    const __half2* h2 = reinterpret_cast<const __half2*>(&raw);
    float v[8];
#pragma unroll
    for (int i = 0; i < 4; i++) {
        const float2 f = __half22float2(h2[i]);
        v[2 * i] = f.x;
        v[2 * i + 1] = f.y;
    }

    float m = v[0];
#pragma unroll
    for (int i = 1; i < 8; i++) m = fmaxf(m, v[i]);
#pragma unroll
    for (int o = 16; o > 0; o >>= 1)
        m = fmaxf(m, __shfl_xor_sync(0xffffffffu, m, o));
    if ((tid & 31) == 0) red_max[tid >> 5] = m;
    __syncthreads();
    float rm = red_max[0];
#pragma unroll
    for (int i = 1; i < 8; i++) rm = fmaxf(rm, red_max[i]);

    float s = 0.0f;
#pragma unroll
    for (int i = 0; i < 8; i++) {
        v[i] = __expf(v[i] - rm);
        s += v[i];
    }
#pragma unroll
    for (int o = 16; o > 0; o >>= 1)
        s += __shfl_xor_sync(0xffffffffu, s, o);
    if ((tid & 31) == 0) red_sum[tid >> 5] = s;
    __syncthreads();
    float total = 0.0f;
#pragma unroll
    for (int i = 0; i < 8; i++) total += red_sum[i];
    const float inv = 1.0f / total;

    uint4 outw;
    __half2* o2 = reinterpret_cast<__half2*>(&outw);
#pragma unroll
    for (int i = 0; i < 4; i++)
        o2[i] = __floats2half2_rn(v[2 * i] * inv, v[2 * i + 1] * inv);
    row[tid] = outw;
}

// ----------------------------------------------------------------------------
// kernel_launch
// Inputs: x[B,S,D], Wq[D,D], bq[D], Wk, bk, Wv, bv ; output [B,S,D] fp32
// ----------------------------------------------------------------------------
extern "C" void kernel_launch(void* const* d_in, const int* in_sizes, int n_in,
                              void* d_out, int out_size)
{
    const float* x  = (const float*)d_in[0];
    const float* Wq = (const float*)d_in[1];
    const float* bq = (const float*)d_in[2];
    const float* Wk = (const float*)d_in[3];
    const float* bk = (const float*)d_in[4];
    const float* Wv = (const float*)d_in[5];
    const float* bv = (const float*)d_in[6];
    float* out = (float*)d_out;

    __half *xh, *qkv, *vt, *s, *wt;
    float *bc;
    cudaGetSymbolAddress((void**)&xh,  g_xh);
    cudaGetSymbolAddress((void**)&qkv, g_qkv);
    cudaGetSymbolAddress((void**)&vt,  g_vt);
    cudaGetSymbolAddress((void**)&s,   g_s);
    cudaGetSymbolAddress((void**)&wt,  g_wt);
    cudaGetSymbolAddress((void**)&bc,  g_bc);

    const int SMEM_DYN = NSTAGE * STAGE_H * (int)sizeof(__half);   // 110592 B
    cudaFuncSetAttribute((const void*)gemm_h<__half, true, true>,
                         cudaFuncAttributeMaxDynamicSharedMemorySize, SMEM_DYN);
    cudaFuncSetAttribute((const void*)gemm_h<__half, false, false>,
                         cudaFuncAttributeMaxDynamicSharedMemorySize, SMEM_DYN);
    cudaFuncSetAttribute((const void*)gemm_h<float, false, false>,
                         cudaFuncAttributeMaxDynamicSharedMemorySize, SMEM_DYN);

    const size_t sQKV = (size_t)SEQ * NQKV;   // per-batch qkv stride
    const size_t sSD  = (size_t)SEQ * DIM;
    const size_t sSS  = (size_t)SEQ * SEQ;

    // 0) x -> fp16 ; W -> half(W^T) concatenated (one launch) ; bias concat
    f32_to_f16<<<(BATCH * SEQ * DIM / 4 + 255) / 256, 256>>>(x, xh);
    {
        const dim3 g(DIM / 32, DIM / 32, 3);
        trans_w3<<<g, 256>>>(Wq, Wk, Wv, wt);
    }
    concat_bias<<<(NQKV + 255) / 256, 256>>>(bq, bk, bv, bc);

    // 1) fused QKV: [8192,2304] = x @ Wcat^T + bcat ; Q slice pre-scaled 1/sqrt(D)
    {
        const dim3 g(NQKV / 128, (BATCH * SEQ) / 128, 1);
        gemm_h<__half, true, true><<<g, 128, SMEM_DYN>>>(
            xh, wt, bc, qkv, DIM, DIM, DIM, NQKV,
            rsqrtf((float)DIM), 0, 0, 0);
    }

    // 2) transpose V slice: [S, D] (ld=NQKV) -> vt [D, S] per batch
    {
        const dim3 g(DIM / 32, SEQ / 32, BATCH);
        trans_h2h<<<g, 256>>>(qkv + 2 * DIM, vt, SEQ, NQKV, sQKV, sSD);
    }

    // 3) scores = Qs @ K^T  (Q already scaled; NT, fp16 out)
    {
        const dim3 g(SEQ / 128, SEQ / 128, BATCH);
        gemm_h<__half, false, false><<<g, 128, SMEM_DYN>>>(
            qkv, qkv + DIM, nullptr, s, DIM, NQKV, NQKV, SEQ,
            1.0f, sQKV, sQKV, sSS);
    }

    // 4) in-place softmax rows (fp16 -> fp16 probs; matrix stays L2-resident)
    softmax2048_h<<<BATCH * SEQ, 256>>>(s);

    // 5) out = P @ V == s[S,S] @ (vt[D,S])^T  (NT, fp32 out)
    {
        const dim3 g(DIM / 128, SEQ / 128, BATCH);
        gemm_h<float, false, false><<<g, 128, SMEM_DYN>>>(
            s, vt, nullptr, out, SEQ, SEQ, SEQ, DIM,
            1.0f, sSS, sSD, sSD);
    }
}